// round 10
// baseline (speedup 1.0000x reference)
#include <cuda_runtime.h>
#include <cuda_bf16.h>
#include <stdint.h>
#include <math.h>

#define TSTEPS 512
#define TOTAL  (TSTEPS * 64 * 1024)      // 33554432 floats per output copy
#define NBLK2  64                        // phase-2 persistent CTAs
#define PLANE_X 33554432u                // 32768*1024 halves per X plane

// ---------------- static device scratch (no allocation) ----------------
__device__ __align__(16) float          g_P[TOTAL];                 // X@Wx+b (fp32)
__device__ __align__(16) __nv_bfloat16  g_Xb[2u * PLANE_X];         // [plane][row 32768][k 1024]
__device__ __align__(16) __nv_bfloat16  g_Wxb[2u * 1024 * 1024];    // [plane][n][k] = Wx[k][n]
__device__ __align__(16) __nv_bfloat16  g_Whb[2u * 1024 * 1024];    // [plane][n][k] = Wh[k][n]
__device__ __align__(16) __nv_bfloat16  g_Sb[2][2 * 65536];         // ping-pong [plane][64 r][1024 k]
__device__ unsigned g_cnt = 0, g_phase = 0;
__device__ __align__(16) unsigned g_pub[NBLK2];   // pub[c]=T: CTA c's columns of S_T are published

#define SWZ(o) ((o) ^ (((o) >> 3) & 0x70))

// ---------------- helpers ----------------
__device__ __forceinline__ uint32_t smem_u32(const void* p) {
    uint32_t a;
    asm("{ .reg .u64 t; cvta.to.shared.u64 t, %1; cvt.u32.u64 %0, t; }" : "=r"(a) : "l"(p));
    return a;
}
__device__ __forceinline__ void ldsm4(uint32_t* r, uint32_t addr) {
    asm volatile("ldmatrix.sync.aligned.m8n8.x4.shared.b16 {%0,%1,%2,%3}, [%4];"
                 : "=r"(r[0]), "=r"(r[1]), "=r"(r[2]), "=r"(r[3]) : "r"(addr));
}
__device__ __forceinline__ void mma_bf16(float* c, const uint32_t* a, const uint32_t* b) {
    asm volatile(
        "mma.sync.aligned.m16n8k16.row.col.f32.bf16.bf16.f32 "
        "{%0,%1,%2,%3}, {%4,%5,%6,%7}, {%8,%9}, {%0,%1,%2,%3};"
        : "+f"(c[0]), "+f"(c[1]), "+f"(c[2]), "+f"(c[3])
        : "r"(a[0]), "r"(a[1]), "r"(a[2]), "r"(a[3]), "r"(b[0]), "r"(b[1]));
}
__device__ __forceinline__ void cp16(uint32_t dst, const void* src) {
    asm volatile("cp.async.cg.shared.global [%0], [%1], 16;" :: "r"(dst), "l"(src) : "memory");
}
__device__ __forceinline__ void cp_commit() { asm volatile("cp.async.commit_group;" ::: "memory"); }
template <int N> __device__ __forceinline__ void cp_wait() {
    asm volatile("cp.async.wait_group %0;" :: "n"(N) : "memory");
}
__device__ __forceinline__ uint4 ldv4(const unsigned* p) {
    uint4 v;
    asm volatile("ld.volatile.global.v4.u32 {%0,%1,%2,%3}, [%4];"
                 : "=r"(v.x), "=r"(v.y), "=r"(v.z), "=r"(v.w) : "l"(p));
    return v;
}
// spin until all 8 producers of slab s have published step >= t
__device__ __forceinline__ void wait_slab(int s, unsigned t) {
    const unsigned* p = &g_pub[s << 3];
    for (;;) {
        uint4 a = ldv4(p), b = ldv4(p + 4);
        unsigned m0 = min(min(a.x, a.y), min(a.z, a.w));
        unsigned m1 = min(min(b.x, b.y), min(b.z, b.w));
        if (min(m0, m1) >= t) return;
    }
}

// ---------------- full grid barrier (init/exit only) ----------------
__device__ __forceinline__ void bar_arrive() {
    __syncthreads();
    if (threadIdx.x == 0) {
        __threadfence();
        unsigned old = atomicAdd(&g_cnt, 1u);
        if (old == NBLK2 - 1) {
            g_cnt = 0;
            __threadfence();
            atomicAdd(&g_phase, 1u);
        }
    }
}
__device__ __forceinline__ void bar_wait(unsigned target) {
    if (threadIdx.x == 0) {
        while ((int)(*((volatile unsigned*)&g_phase) - target) < 0) { }
    }
    __syncthreads();
}

// ---------------- conversion kernels ----------------
__global__ void conv_w(const float* __restrict__ W, int which)
{
    __nv_bfloat16* out = which ? g_Whb : g_Wxb;
    __shared__ float sm[64][65];
    const int n0 = blockIdx.x << 6, k0 = blockIdx.y << 6;
    const int tid = threadIdx.x;
#pragma unroll
    for (int it = 0; it < 16; it++) {
        int e = it * 256 + tid;
        int kk = e >> 6, nn = e & 63;
        sm[kk][nn] = W[(size_t)(k0 + kk) * 1024 + n0 + nn];
    }
    __syncthreads();
#pragma unroll
    for (int it = 0; it < 16; it++) {
        int e = it * 256 + tid;
        int nn = e >> 6, kk = e & 63;
        float v = sm[kk][nn];
        __nv_bfloat16 hi = __float2bfloat16(v);
        __nv_bfloat16 lo = __float2bfloat16(v - __bfloat162float(hi));
        size_t o = (size_t)(n0 + nn) * 1024 + k0 + kk;
        out[o]            = hi;
        out[o + 1048576u] = lo;
    }
}

__global__ void conv_x(const float* __restrict__ X)
{
    int v = blockIdx.x * 256 + threadIdx.x;
#pragma unroll
    for (int i = 0; i < 8; i++) {
        int f4 = v + i * 1048576;
        const float4 x = ((const float4*)X)[f4];
        size_t e0 = (size_t)f4 << 2;
        float xs[4] = {x.x, x.y, x.z, x.w};
        unsigned short hs[4], ls[4];
#pragma unroll
        for (int q = 0; q < 4; q++) {
            __nv_bfloat16 hv = __float2bfloat16(xs[q]);
            __nv_bfloat16 lv = __float2bfloat16(xs[q] - __bfloat162float(hv));
            hs[q] = __bfloat16_as_ushort(hv); ls[q] = __bfloat16_as_ushort(lv);
        }
        *(ushort4*)(g_Xb + e0)           = make_ushort4(hs[0], hs[1], hs[2], hs[3]);
        *(ushort4*)(g_Xb + e0 + PLANE_X) = make_ushort4(ls[0], ls[1], ls[2], ls[3]);
    }
}

// ---------------- phase 1: P = X@Wx + b (unchanged — 482us, tensor 70%) ----------------
#define P1_SMEM 131072

#define P1_ISSUE(kt) do {                                                              \
    _Pragma("unroll")                                                                  \
    for (int i = 0; i < 8; i++) {                                                      \
        int id = i * 256 + tid;                                                        \
        int ku = id & 7, r = (id >> 3) & 127, p = id >> 10;                            \
        uint32_t off = (uint32_t)((((kt) & 1) << 16) + (p << 14)                       \
                       + SWZ((uint32_t)(r * 128 + ku * 16)));                          \
        cp16(su + off,         g_Xb  + (size_t)p * PLANE_X                             \
             + (size_t)(m0 + r) * 1024 + (kt) * 64 + ku * 8);                          \
        cp16(su + off + 32768, g_Wxb + (size_t)p * 1048576                             \
             + (size_t)(col0 + r) * 1024 + (kt) * 64 + ku * 8);                        \
    }                                                                                  \
    cp_commit();                                                                       \
} while (0)

__global__ void __launch_bounds__(256, 1)
gemm_p1(const float* __restrict__ bias)
{
    extern __shared__ __align__(1024) char dyn[];
    const uint32_t su = smem_u32(dyn);
    const int tid = threadIdx.x, wid = tid >> 5, lane = tid & 31;
    const int col0 = blockIdx.x << 7, m0 = blockIdx.y << 7;

    const int laneR = lane & 7, idq = lane >> 3;
    const int rowA = laneR + ((idq & 1) << 3), k8A = (idq >> 1) << 3;
    const int nB   = laneR + ((idq >> 1) << 3), k8B = (idq & 1) << 3;
    uint32_t swzA[4], swzB[4];
#pragma unroll
    for (int kc = 0; kc < 4; kc++) {
        swzA[kc] = SWZ((uint32_t)(rowA * 128 + (kc * 16 + k8A) * 2));
        swzB[kc] = SWZ((uint32_t)(nB   * 128 + (kc * 16 + k8B) * 2));
    }

    float c[16][4];
#pragma unroll
    for (int q = 0; q < 16; q++)
#pragma unroll
        for (int j = 0; j < 4; j++) c[q][j] = 0.0f;

    P1_ISSUE(0);
    for (int kt = 0; kt < 16; kt++) {
        if (kt < 15) { P1_ISSUE(kt + 1); cp_wait<1>(); } else { cp_wait<0>(); }
        __syncthreads();
        const uint32_t Ab = su + ((kt & 1) << 16) + (wid << 11);
        const uint32_t Bb = su + ((kt & 1) << 16) + 32768;
#pragma unroll
        for (int kc = 0; kc < 4; kc++) {
            uint32_t ah[4], al[4], bb[32];
            ldsm4(ah, Ab + swzA[kc]);
            ldsm4(al, Ab + 16384 + swzA[kc]);
#pragma unroll
            for (int q = 0; q < 8; q++) ldsm4(&bb[q * 4], Bb + q * 2048 + swzB[kc]);
#pragma unroll
            for (int q = 0; q < 8; q++) {
                mma_bf16(c[2 * q],     ah, &bb[q * 4]);
                mma_bf16(c[2 * q + 1], ah, &bb[q * 4 + 2]);
            }
#pragma unroll
            for (int q = 0; q < 8; q++) {
                mma_bf16(c[2 * q],     al, &bb[q * 4]);
                mma_bf16(c[2 * q + 1], al, &bb[q * 4 + 2]);
            }
#pragma unroll
            for (int q = 0; q < 8; q++) ldsm4(&bb[q * 4], Bb + 16384 + q * 2048 + swzB[kc]);
#pragma unroll
            for (int q = 0; q < 8; q++) {
                mma_bf16(c[2 * q],     ah, &bb[q * 4]);
                mma_bf16(c[2 * q + 1], ah, &bb[q * 4 + 2]);
            }
        }
        __syncthreads();
    }

    const int r0 = m0 + (wid << 4) + (lane >> 2);
#pragma unroll
    for (int nb = 0; nb < 16; nb++) {
        int colp = col0 + nb * 8 + ((lane & 3) << 1);
        float2 bb = *(const float2*)&bias[colp];
        *(float2*)&g_P[(size_t)r0 * 1024 + colp]       = make_float2(c[nb][0] + bb.x, c[nb][1] + bb.y);
        *(float2*)&g_P[(size_t)(r0 + 8) * 1024 + colp] = make_float2(c[nb][2] + bb.x, c[nb][3] + bb.y);
    }
}

// ---------------- phase 2: persistent recurrence, fine-grained flags ----------------
// 64 CTAs x 256 thr. warp: rg = wid&3 (16 rows of 128 hi/lo), ch = wid>>2 (8 of 16 cols).
// No per-step global barrier: pub[c] flags gate slab issue (producers 8s..8s+7 per slab).
// Buffer-overwrite safety: finishing step t required all 64 pubs >= t (slabs span all
// producers), so everyone has finished their step t-1 reads of the buffer we overwrite.
// smem: A ring 4 x 32K @0 | Wh 64K @131072 | pP 4K @196608 | stg @200704 | red @205056
#define P2_SMEM 207232

#define P2_ISSUE(ss) do {                                                              \
    _Pragma("unroll")                                                                  \
    for (int i = 0; i < 8; i++) {                                                      \
        int id = i * 256 + tid;                                                        \
        int ku = id & 15, r = (id >> 4) & 63, p = id >> 10;                            \
        uint32_t off = (uint32_t)((((ss) & 3) << 15)                                   \
                       + ((((p << 2) | (r >> 4)) * 2 + (ku >> 3)) << 11)               \
                       + SWZ((uint32_t)((r & 15) * 128 + (ku & 7) * 16)));             \
        cp16(su + off, Sb + (size_t)p * 65536 + (size_t)r * 1024 + (ss) * 128 + ku * 8); \
    }                                                                                  \
    cp_commit();                                                                       \
} while (0)

__global__ void __launch_bounds__(256, 1)
rnn_p2(const float* __restrict__ state0, float* __restrict__ out)
{
    extern __shared__ __align__(1024) char dyn[];
    const uint32_t su = smem_u32(dyn);
    const int tid = threadIdx.x, wid = tid >> 5, lane = tid & 31;
    const int rg = wid & 3;              // rowgroup (16 rows)
    const int ch = wid >> 2;             // column half (8 of 16 cols)
    const int n0 = blockIdx.x << 4;      // CTA owns 16 columns

    const unsigned base = *((volatile unsigned*)&g_phase);

    const int laneR = lane & 7, idq = lane >> 3;
    const int rowA = laneR + ((idq & 1) << 3), k8A = (idq >> 1) << 3;
    const int nB   = laneR + ((idq >> 1) << 3), k8B = (idq & 1) << 3;
    uint32_t swzA[4], swzB[4];
#pragma unroll
    for (int kc = 0; kc < 4; kc++) {
        swzA[kc] = SWZ((uint32_t)(rowA * 128 + (kc * 16 + k8A) * 2));
        swzB[kc] = SWZ((uint32_t)(nB   * 128 + (kc * 16 + k8B) * 2));
    }

    // resident Wh slice @131072: [p][slab16(k64)][n16][128B] swizzled (64 KB)
#pragma unroll 4
    for (int i = 0; i < 16; i++) {
        int id = i * 256 + tid;                  // 4096 uint4
        int ku = id & 127, n = (id >> 7) & 15, p = id >> 11;
        uint4 v = *(const uint4*)(g_Whb + (size_t)p * 1048576 + (size_t)(n0 + n) * 1024 + ku * 8);
        uint32_t off = 131072u + (uint32_t)((((p << 4) + (ku >> 3)) << 11)
                       + SWZ((uint32_t)(n * 128 + (ku & 7) * 16)));
        *(uint4*)(dyn + off) = v;
    }
    // init ping state from state0 (1 float4/thread, 64 CTAs x 256 = 16384)
    {
        int f4 = blockIdx.x * 256 + tid;
        float4 x = ((const float4*)state0)[f4];
        size_t e0 = (size_t)f4 << 2;
        float xs[4] = {x.x, x.y, x.z, x.w};
        unsigned short hs[4], ls[4];
#pragma unroll
        for (int q = 0; q < 4; q++) {
            __nv_bfloat16 hv = __float2bfloat16(xs[q]);
            __nv_bfloat16 lv = __float2bfloat16(xs[q] - __bfloat162float(hv));
            hs[q] = __bfloat16_as_ushort(hv); ls[q] = __bfloat16_as_ushort(lv);
        }
        *(ushort4*)(&g_Sb[0][e0])         = make_ushort4(hs[0], hs[1], hs[2], hs[3]);
        *(ushort4*)(&g_Sb[0][e0 + 65536]) = make_ushort4(ls[0], ls[1], ls[2], ls[3]);
    }
    bar_arrive();                                 // pub[] is all-zero here (reset at exit)
    bar_wait(base + 1);

    float* pP   = (float*)(dyn + 196608);         // [64][16]
    float* stg  = (float*)(dyn + 200704);         // [64][17]
    float* psum = (float*)(dyn + 205056);         // [16][16]
    float* psq  = (float*)(dyn + 206080);         // [16][16]
    float* cmu  = (float*)(dyn + 207104);         // [16]
    float* cinv = (float*)(dyn + 207168);         // [16]
    const int j = tid & 15, hg = tid >> 4;

    for (int t = 0; t < TSTEPS; t++) {
        const unsigned tu = (unsigned)t;          // need pub >= t (t=0 trivially true)
        const __nv_bfloat16* Sb = g_Sb[t & 1];

        if (tid == 0) { wait_slab(0, tu); wait_slab(1, tu); wait_slab(2, tu); }
        __syncthreads();

        // P[t] prefetch: own group, committed first (retired by u=0 wait)
        cp16(su + 196608 + tid * 16,
             g_P + (size_t)t * 65536 + (size_t)(tid >> 2) * 1024 + n0 + ((tid & 3) << 2));
        cp_commit();
        P2_ISSUE(0); P2_ISSUE(1); P2_ISSUE(2);

        float c0[4] = {0.0f, 0.0f, 0.0f, 0.0f};
        float cb[4] = {0.0f, 0.0f, 0.0f, 0.0f};
        for (int u = 0; u < 8; u++) {
            if (u < 6) cp_wait<2>(); else if (u == 6) cp_wait<1>(); else cp_wait<0>();
            if (tid == 0 && u < 5) wait_slab(u + 3, tu);
            __syncthreads();
            if (u < 5) P2_ISSUE(u + 3);            // writes stage (u-1)&3 — safe post-sync
            const uint32_t Ab  = su + ((u & 3) << 15) + ((rg * 2) << 11);
            const uint32_t Bb0 = su + 131072 + ((u * 2) << 11);
#pragma unroll
            for (int kc = 0; kc < 8; kc++) {
                uint32_t ah[4], al[4], bh[4], bl4[4];
                uint32_t Aq = Ab + ((kc >> 2) << 11) + swzA[kc & 3];
                uint32_t Bq = Bb0 + ((kc >> 2) << 11) + swzB[kc & 3];
                ldsm4(ah, Aq);
                ldsm4(al, Aq + 16384);             // A lo plane
                ldsm4(bh, Bq);
                ldsm4(bl4, Bq + 32768);            // Wh lo plane
                if (ch == 0) {
                    mma_bf16(c0, ah, bh);
                    mma_bf16(cb, al, bh);
                    mma_bf16(c0, ah, bl4);
                } else {
                    mma_bf16(c0, ah, bh + 2);
                    mma_bf16(cb, al, bh + 2);
                    mma_bf16(c0, ah, bl4 + 2);
                }
            }
        }

        // ---- epilogue ----
        {
            int rr = (rg << 4) + (lane >> 2), cc = (ch << 3) + ((lane & 3) << 1);
            stg[rr * 17 + cc]           = c0[0] + cb[0];
            stg[rr * 17 + cc + 1]       = c0[1] + cb[1];
            stg[(rr + 8) * 17 + cc]     = c0[2] + cb[2];
            stg[(rr + 8) * 17 + cc + 1] = c0[3] + cb[3];
        }
        __syncthreads();

        float hv[4], ps = 0.0f, pq = 0.0f;
#pragma unroll
        for (int i = 0; i < 4; i++) {
            int r = (hg << 2) + i;
            float z = stg[r * 17 + j] + pP[r * 16 + j];
            float h = tanhf(z);
            hv[i] = h; ps += h; pq += h * h;
        }
        psum[hg * 16 + j] = ps;
        psq[hg * 16 + j]  = pq;
        __syncthreads();
        if (tid < 16) {
            float s = 0.0f, q = 0.0f;
#pragma unroll
            for (int g2 = 0; g2 < 16; g2++) { s += psum[g2 * 16 + tid]; q += psq[g2 * 16 + tid]; }
            float mu  = s * (1.0f / 64.0f);
            float var = q * (1.0f / 64.0f) - mu * mu;
            cmu[tid]  = mu;
            cinv[tid] = rsqrtf(var + 1e-5f);
        }
        __syncthreads();

        float mu = cmu[j], inv = cinv[j];
        float sv[4];
        {
            __nv_bfloat16* Sn = g_Sb[(t + 1) & 1];
#pragma unroll
            for (int i = 0; i < 4; i++) {
                int r = (hg << 2) + i;
                sv[i] = (hv[i] - mu) * inv;
                __nv_bfloat16 hb = __float2bfloat16(sv[i]);
                __nv_bfloat16 lb = __float2bfloat16(sv[i] - __bfloat162float(hb));
                Sn[(size_t)r * 1024 + n0 + j]         = hb;
                Sn[65536 + (size_t)r * 1024 + n0 + j] = lb;
            }
        }
        __syncthreads();
        if (tid == 0) {
            __threadfence();
            *((volatile unsigned*)&g_pub[blockIdx.x]) = (unsigned)(t + 1);   // release S_{t+1}
        }
        // out stores in the publish shadow
#pragma unroll
        for (int i = 0; i < 4; i++) {
            int r = (hg << 2) + i;
            size_t o = ((size_t)t * 64 + r) * 1024 + n0 + j;
            out[o]                 = sv[i];
            out[o + (size_t)TOTAL] = sv[i];
        }
    }

    // exit barrier + replay-safe reset of pub flags
    bar_arrive();
    bar_wait(base + 2);
    if (tid == 0) *((volatile unsigned*)&g_pub[blockIdx.x]) = 0;
}

// ---------------------------------------------------------------------------
extern "C" void kernel_launch(void* const* d_in, const int* in_sizes, int n_in,
                              void* d_out, int out_size)
{
    const float* X    = (const float*)d_in[0];   // [512,64,1024]
    const float* S0   = (const float*)d_in[1];   // [1,64,1024]
    const float* Wx   = (const float*)d_in[2];   // [1024,1024]
    const float* Wh   = (const float*)d_in[3];   // [1024,1024]
    const float* bias = (const float*)d_in[4];   // [1024]
    float* out = (float*)d_out;

    cudaFuncSetAttribute(gemm_p1, cudaFuncAttributeMaxDynamicSharedMemorySize, P1_SMEM);
    cudaFuncSetAttribute(rnn_p2,  cudaFuncAttributeMaxDynamicSharedMemorySize, P2_SMEM);

    conv_w<<<dim3(16, 16), 256>>>(Wx, 0);
    conv_w<<<dim3(16, 16), 256>>>(Wh, 1);
    conv_x<<<4096, 256>>>(X);
    gemm_p1<<<dim3(8, 256), 256, P1_SMEM>>>(bias);
    rnn_p2<<<NBLK2, 256, P2_SMEM>>>(S0, out);
}

// round 11
// speedup vs baseline: 1.6691x; 1.6691x over previous
#include <cuda_runtime.h>
#include <cuda_bf16.h>
#include <stdint.h>
#include <math.h>

#define TSTEPS 512
#define TOTAL  (TSTEPS * 64 * 1024)      // 33554432 floats per output copy
#define NBLK2  64                        // phase-2 persistent CTAs
#define PLANE_X 33554432u                // 32768*1024 halves per X plane

// ---------------- static device scratch (no allocation) ----------------
__device__ __align__(16) float          g_P[TOTAL];                 // X@Wx+b (fp32)
__device__ __align__(16) __nv_bfloat16  g_Xb[2u * PLANE_X];         // [plane][row 32768][k 1024]
__device__ __align__(16) __nv_bfloat16  g_Wxb[2u * 1024 * 1024];    // [plane][n][k] = Wx[k][n]
__device__ __align__(16) __nv_bfloat16  g_Whb[2u * 1024 * 1024];    // [plane][n][k] = Wh[k][n]
__device__ __align__(16) __nv_bfloat16  g_Sb[2][2 * 65536];         // ping-pong [plane][64 r][1024 k]
__device__ unsigned g_cnt = 0, g_phase = 0;

#define SWZ(o) ((o) ^ (((o) >> 3) & 0x70))

// ---------------- helpers ----------------
__device__ __forceinline__ uint32_t smem_u32(const void* p) {
    uint32_t a;
    asm("{ .reg .u64 t; cvta.to.shared.u64 t, %1; cvt.u32.u64 %0, t; }" : "=r"(a) : "l"(p));
    return a;
}
__device__ __forceinline__ void ldsm4(uint32_t* r, uint32_t addr) {
    asm volatile("ldmatrix.sync.aligned.m8n8.x4.shared.b16 {%0,%1,%2,%3}, [%4];"
                 : "=r"(r[0]), "=r"(r[1]), "=r"(r[2]), "=r"(r[3]) : "r"(addr));
}
__device__ __forceinline__ void mma_bf16(float* c, const uint32_t* a, const uint32_t* b) {
    asm volatile(
        "mma.sync.aligned.m16n8k16.row.col.f32.bf16.bf16.f32 "
        "{%0,%1,%2,%3}, {%4,%5,%6,%7}, {%8,%9}, {%0,%1,%2,%3};"
        : "+f"(c[0]), "+f"(c[1]), "+f"(c[2]), "+f"(c[3])
        : "r"(a[0]), "r"(a[1]), "r"(a[2]), "r"(a[3]), "r"(b[0]), "r"(b[1]));
}
__device__ __forceinline__ void cp16(uint32_t dst, const void* src) {
    asm volatile("cp.async.cg.shared.global [%0], [%1], 16;" :: "r"(dst), "l"(src) : "memory");
}
__device__ __forceinline__ void cp_commit() { asm volatile("cp.async.commit_group;" ::: "memory"); }
template <int N> __device__ __forceinline__ void cp_wait() {
    asm volatile("cp.async.wait_group %0;" :: "n"(N) : "memory");
}
// tanh(z) = 1 - 2/(exp(2z)+1) via MUFU.EX2 + MUFU.RCP (no libm FMA tail; |err| ~1e-6)
__device__ __forceinline__ float fast_tanh(float z) {
    float e, r;
    asm("ex2.approx.ftz.f32 %0, %1;" : "=f"(e) : "f"(z * 2.8853900817779268f));
    asm("rcp.approx.ftz.f32 %0, %1;" : "=f"(r) : "f"(e + 1.0f));
    return fmaf(-2.0f, r, 1.0f);
}

// ---------------- grid barrier (64 CTAs, monotonic phase; r6-proven) ----------------
__device__ __forceinline__ void grid_bar() {
    __syncthreads();
    if (threadIdx.x == 0) {
        __threadfence();
        unsigned ph = *((volatile unsigned*)&g_phase);
        unsigned old = atomicAdd(&g_cnt, 1u);
        if (old == NBLK2 - 1) {
            g_cnt = 0;
            __threadfence();
            atomicExch(&g_phase, ph + 1u);
        } else {
            while (*((volatile unsigned*)&g_phase) == ph) { }
        }
        __threadfence();
    }
    __syncthreads();
}

// ---------------- conversion kernels ----------------
__global__ void conv_w(const float* __restrict__ W, int which)
{
    __nv_bfloat16* out = which ? g_Whb : g_Wxb;
    __shared__ float sm[64][65];
    const int n0 = blockIdx.x << 6, k0 = blockIdx.y << 6;
    const int tid = threadIdx.x;
#pragma unroll
    for (int it = 0; it < 16; it++) {
        int e = it * 256 + tid;
        int kk = e >> 6, nn = e & 63;
        sm[kk][nn] = W[(size_t)(k0 + kk) * 1024 + n0 + nn];
    }
    __syncthreads();
#pragma unroll
    for (int it = 0; it < 16; it++) {
        int e = it * 256 + tid;
        int nn = e >> 6, kk = e & 63;
        float v = sm[kk][nn];
        __nv_bfloat16 hi = __float2bfloat16(v);
        __nv_bfloat16 lo = __float2bfloat16(v - __bfloat162float(hi));
        size_t o = (size_t)(n0 + nn) * 1024 + k0 + kk;
        out[o]            = hi;
        out[o + 1048576u] = lo;
    }
}

__global__ void conv_x(const float* __restrict__ X)
{
    int v = blockIdx.x * 256 + threadIdx.x;
#pragma unroll
    for (int i = 0; i < 8; i++) {
        int f4 = v + i * 1048576;
        const float4 x = ((const float4*)X)[f4];
        size_t e0 = (size_t)f4 << 2;
        float xs[4] = {x.x, x.y, x.z, x.w};
        unsigned short hs[4], ls[4];
#pragma unroll
        for (int q = 0; q < 4; q++) {
            __nv_bfloat16 hv = __float2bfloat16(xs[q]);
            __nv_bfloat16 lv = __float2bfloat16(xs[q] - __bfloat162float(hv));
            hs[q] = __bfloat16_as_ushort(hv); ls[q] = __bfloat16_as_ushort(lv);
        }
        *(ushort4*)(g_Xb + e0)           = make_ushort4(hs[0], hs[1], hs[2], hs[3]);
        *(ushort4*)(g_Xb + e0 + PLANE_X) = make_ushort4(ls[0], ls[1], ls[2], ls[3]);
    }
}

// ---------------- phase 1: P = X@Wx + b (unchanged — 482us, tensor 70%) ----------------
#define P1_SMEM 131072

#define P1_ISSUE(kt) do {                                                              \
    _Pragma("unroll")                                                                  \
    for (int i = 0; i < 8; i++) {                                                      \
        int id = i * 256 + tid;                                                        \
        int ku = id & 7, r = (id >> 3) & 127, p = id >> 10;                            \
        uint32_t off = (uint32_t)((((kt) & 1) << 16) + (p << 14)                       \
                       + SWZ((uint32_t)(r * 128 + ku * 16)));                          \
        cp16(su + off,         g_Xb  + (size_t)p * PLANE_X                             \
             + (size_t)(m0 + r) * 1024 + (kt) * 64 + ku * 8);                          \
        cp16(su + off + 32768, g_Wxb + (size_t)p * 1048576                             \
             + (size_t)(col0 + r) * 1024 + (kt) * 64 + ku * 8);                        \
    }                                                                                  \
    cp_commit();                                                                       \
} while (0)

__global__ void __launch_bounds__(256, 1)
gemm_p1(const float* __restrict__ bias)
{
    extern __shared__ __align__(1024) char dyn[];
    const uint32_t su = smem_u32(dyn);
    const int tid = threadIdx.x, wid = tid >> 5, lane = tid & 31;
    const int col0 = blockIdx.x << 7, m0 = blockIdx.y << 7;

    const int laneR = lane & 7, idq = lane >> 3;
    const int rowA = laneR + ((idq & 1) << 3), k8A = (idq >> 1) << 3;
    const int nB   = laneR + ((idq >> 1) << 3), k8B = (idq & 1) << 3;
    uint32_t swzA[4], swzB[4];
#pragma unroll
    for (int kc = 0; kc < 4; kc++) {
        swzA[kc] = SWZ((uint32_t)(rowA * 128 + (kc * 16 + k8A) * 2));
        swzB[kc] = SWZ((uint32_t)(nB   * 128 + (kc * 16 + k8B) * 2));
    }

    float c[16][4];
#pragma unroll
    for (int q = 0; q < 16; q++)
#pragma unroll
        for (int j = 0; j < 4; j++) c[q][j] = 0.0f;

    P1_ISSUE(0);
    for (int kt = 0; kt < 16; kt++) {
        if (kt < 15) { P1_ISSUE(kt + 1); cp_wait<1>(); } else { cp_wait<0>(); }
        __syncthreads();
        const uint32_t Ab = su + ((kt & 1) << 16) + (wid << 11);
        const uint32_t Bb = su + ((kt & 1) << 16) + 32768;
#pragma unroll
        for (int kc = 0; kc < 4; kc++) {
            uint32_t ah[4], al[4], bb[32];
            ldsm4(ah, Ab + swzA[kc]);
            ldsm4(al, Ab + 16384 + swzA[kc]);
#pragma unroll
            for (int q = 0; q < 8; q++) ldsm4(&bb[q * 4], Bb + q * 2048 + swzB[kc]);
#pragma unroll
            for (int q = 0; q < 8; q++) {
                mma_bf16(c[2 * q],     ah, &bb[q * 4]);
                mma_bf16(c[2 * q + 1], ah, &bb[q * 4 + 2]);
            }
#pragma unroll
            for (int q = 0; q < 8; q++) {
                mma_bf16(c[2 * q],     al, &bb[q * 4]);
                mma_bf16(c[2 * q + 1], al, &bb[q * 4 + 2]);
            }
#pragma unroll
            for (int q = 0; q < 8; q++) ldsm4(&bb[q * 4], Bb + 16384 + q * 2048 + swzB[kc]);
#pragma unroll
            for (int q = 0; q < 8; q++) {
                mma_bf16(c[2 * q],     ah, &bb[q * 4]);
                mma_bf16(c[2 * q + 1], ah, &bb[q * 4 + 2]);
            }
        }
        __syncthreads();
    }

    const int r0 = m0 + (wid << 4) + (lane >> 2);
#pragma unroll
    for (int nb = 0; nb < 16; nb++) {
        int colp = col0 + nb * 8 + ((lane & 3) << 1);
        float2 bb = *(const float2*)&bias[colp];
        *(float2*)&g_P[(size_t)r0 * 1024 + colp]       = make_float2(c[nb][0] + bb.x, c[nb][1] + bb.y);
        *(float2*)&g_P[(size_t)(r0 + 8) * 1024 + colp] = make_float2(c[nb][2] + bb.x, c[nb][3] + bb.y);
    }
}

// ---------------- phase 2: persistent recurrence (r6 base + ring-4 + fast tanh) ----------------
// 64 CTAs x 128 thr (4 warps, 16 rows each; all 16 cols per warp). CTA owns 16 columns.
// smem: A ring 4 x 32K @0 | Wh 64K @131072 | stg @196608 | red @200960
#define P2_SMEM 202240

#define P2_ISSUE(ss) do {                                                              \
    _Pragma("unroll")                                                                  \
    for (int i = 0; i < 16; i++) {                                                     \
        int id = i * 128 + tid;                                                        \
        int ku = id & 15, r = (id >> 4) & 63, p = id >> 10;                            \
        uint32_t off = (uint32_t)((((ss) & 3) << 15)                                   \
                       + (((p * 4 + (r >> 4)) * 2 + (ku >> 3)) << 11)                  \
                       + SWZ((uint32_t)((r & 15) * 128 + (ku & 7) * 16)));             \
        cp16(su + off, Sb + (size_t)p * 65536 + (size_t)r * 1024 + (ss) * 128 + ku * 8); \
    }                                                                                  \
    cp_commit();                                                                       \
} while (0)

__global__ void __launch_bounds__(128, 1)
rnn_p2(const float* __restrict__ state0, float* __restrict__ out)
{
    extern __shared__ __align__(1024) char dyn[];
    const uint32_t su = smem_u32(dyn);
    const int tid = threadIdx.x, wid = tid >> 5, lane = tid & 31;
    const int n0 = blockIdx.x << 4;

    const int laneR = lane & 7, idq = lane >> 3;
    const int rowA = laneR + ((idq & 1) << 3), k8A = (idq >> 1) << 3;
    const int nB   = laneR + ((idq >> 1) << 3), k8B = (idq & 1) << 3;
    uint32_t swzA[4], swzB[4];
#pragma unroll
    for (int kc = 0; kc < 4; kc++) {
        swzA[kc] = SWZ((uint32_t)(rowA * 128 + (kc * 16 + k8A) * 2));
        swzB[kc] = SWZ((uint32_t)(nB   * 128 + (kc * 16 + k8B) * 2));
    }

    // resident Wh slice @131072: [2p][16 s64][16 n][128B] swizzled (64 KB)
#pragma unroll 4
    for (int i = 0; i < 32; i++) {
        int id = i * 128 + tid;
        int ku = id & 127, n = (id >> 7) & 15, p = id >> 11;
        uint4 v = *(const uint4*)(g_Whb + (size_t)p * 1048576 + (size_t)(n0 + n) * 1024 + ku * 8);
        uint32_t off = 131072u + (uint32_t)(((p * 16 + (ku >> 3)) << 11)
                       + SWZ((uint32_t)(n * 128 + (ku & 7) * 16)));
        *(uint4*)(dyn + off) = v;
    }
    // init ping state from state0
    {
        int id = blockIdx.x * 128 + tid;
#pragma unroll
        for (int i = 0; i < 2; i++) {
            int f4 = id + i * 8192;                // 16384 float4
            float4 x = ((const float4*)state0)[f4];
            size_t e0 = (size_t)f4 << 2;
            float xs[4] = {x.x, x.y, x.z, x.w};
            unsigned short hs[4], ls[4];
#pragma unroll
            for (int q = 0; q < 4; q++) {
                __nv_bfloat16 hv = __float2bfloat16(xs[q]);
                __nv_bfloat16 lv = __float2bfloat16(xs[q] - __bfloat162float(hv));
                hs[q] = __bfloat16_as_ushort(hv); ls[q] = __bfloat16_as_ushort(lv);
            }
            *(ushort4*)(&g_Sb[0][e0])         = make_ushort4(hs[0], hs[1], hs[2], hs[3]);
            *(ushort4*)(&g_Sb[0][e0 + 65536]) = make_ushort4(ls[0], ls[1], ls[2], ls[3]);
        }
    }
    __threadfence();
    grid_bar();

    float* stg  = (float*)(dyn + 196608);          // [64][17]
    float* psum = (float*)(dyn + 200960);          // [8][16]
    float* psq  = (float*)(dyn + 201472);          // [8][16]
    float* cmu  = (float*)(dyn + 201984);          // [16]
    float* cinv = (float*)(dyn + 202048);          // [16]
    const int j = tid & 15, hg = tid >> 4;

    for (int t = 0; t < TSTEPS; t++) {
        const __nv_bfloat16* Sb = g_Sb[t & 1];
        float c0[4] = {0, 0, 0, 0}, c1[4] = {0, 0, 0, 0};

        P2_ISSUE(0); P2_ISSUE(1); P2_ISSUE(2);
        for (int s = 0; s < 8; s++) {
            if (s <= 5) cp_wait<2>(); else if (s == 6) cp_wait<1>(); else cp_wait<0>();
            __syncthreads();
            if (s < 5) P2_ISSUE(s + 3);            // overwrites stage (s-1)&3 — dead post-sync
#pragma unroll
            for (int kc = 0; kc < 8; kc++) {
                uint32_t ah[4], al[4], bh[4], bl[4];
                uint32_t Ab = su + ((s & 3) << 15) + (wid << 12) + ((kc >> 2) << 11);
                uint32_t Bb = su + 131072 + ((s * 2 + (kc >> 2)) << 11);
                ldsm4(ah, Ab + swzA[kc & 3]);
                ldsm4(al, Ab + 16384 + swzA[kc & 3]);
                ldsm4(bh, Bb + swzB[kc & 3]);
                ldsm4(bl, Bb + 32768 + swzB[kc & 3]);
                mma_bf16(c0, ah, bh); mma_bf16(c1, ah, bh + 2);
                mma_bf16(c0, al, bh); mma_bf16(c1, al, bh + 2);
                mma_bf16(c0, ah, bl); mma_bf16(c1, ah, bl + 2);
            }
            __syncthreads();
        }

        // ---- epilogue: stage C, +P, tanh, per-column BN (block-local) ----
        {
            int rr = (wid << 4) + (lane >> 2);
            int cc = (lane & 3) << 1;
            stg[rr * 17 + cc]           = c0[0];
            stg[rr * 17 + cc + 1]       = c0[1];
            stg[(rr + 8) * 17 + cc]     = c0[2];
            stg[(rr + 8) * 17 + cc + 1] = c0[3];
            stg[rr * 17 + 8 + cc]           = c1[0];
            stg[rr * 17 + 8 + cc + 1]       = c1[1];
            stg[(rr + 8) * 17 + 8 + cc]     = c1[2];
            stg[(rr + 8) * 17 + 8 + cc + 1] = c1[3];
        }
        __syncthreads();

        float hv[8], ps = 0.0f, pq = 0.0f;
        const float* Pt = g_P + (size_t)t * 65536 + n0 + j;
#pragma unroll
        for (int i = 0; i < 8; i++) {
            int r = hg * 8 + i;
            float z = stg[r * 17 + j] + __ldg(&Pt[(size_t)r * 1024]);
            float h = fast_tanh(z);
            hv[i] = h; ps += h; pq += h * h;
        }
        psum[hg * 16 + j] = ps;
        psq[hg * 16 + j]  = pq;
        __syncthreads();
        if (tid < 16) {
            float s = 0.0f, q = 0.0f;
#pragma unroll
            for (int g2 = 0; g2 < 8; g2++) { s += psum[g2 * 16 + tid]; q += psq[g2 * 16 + tid]; }
            float mu  = s * (1.0f / 64.0f);
            float var = q * (1.0f / 64.0f) - mu * mu;
            cmu[tid]  = mu;
            cinv[tid] = rsqrtf(var + 1e-5f);
        }
        __syncthreads();
        {
            float mu = cmu[j], inv = cinv[j];
            __nv_bfloat16* Sn = g_Sb[(t + 1) & 1];
#pragma unroll
            for (int i = 0; i < 8; i++) {
                int r = hg * 8 + i;
                float sv = (hv[i] - mu) * inv;
                size_t o = ((size_t)t * 64 + r) * 1024 + n0 + j;
                out[o]                 = sv;
                out[o + (size_t)TOTAL] = sv;
                __nv_bfloat16 hb = __float2bfloat16(sv);
                __nv_bfloat16 lb = __float2bfloat16(sv - __bfloat162float(hb));
                Sn[(size_t)r * 1024 + n0 + j]         = hb;
                Sn[65536 + (size_t)r * 1024 + n0 + j] = lb;
            }
        }
        __threadfence();
        grid_bar();
    }
}

// ---------------------------------------------------------------------------
extern "C" void kernel_launch(void* const* d_in, const int* in_sizes, int n_in,
                              void* d_out, int out_size)
{
    const float* X    = (const float*)d_in[0];   // [512,64,1024]
    const float* S0   = (const float*)d_in[1];   // [1,64,1024]
    const float* Wx   = (const float*)d_in[2];   // [1024,1024]
    const float* Wh   = (const float*)d_in[3];   // [1024,1024]
    const float* bias = (const float*)d_in[4];   // [1024]
    float* out = (float*)d_out;

    cudaFuncSetAttribute(gemm_p1, cudaFuncAttributeMaxDynamicSharedMemorySize, P1_SMEM);
    cudaFuncSetAttribute(rnn_p2,  cudaFuncAttributeMaxDynamicSharedMemorySize, P2_SMEM);

    conv_w<<<dim3(16, 16), 256>>>(Wx, 0);
    conv_w<<<dim3(16, 16), 256>>>(Wh, 1);
    conv_x<<<4096, 256>>>(X);
    gemm_p1<<<dim3(8, 256), 256, P1_SMEM>>>(bias);
    rnn_p2<<<NBLK2, 128, P2_SMEM>>>(S0, out);
}

// round 14
// speedup vs baseline: 1.7012x; 1.0192x over previous
#include <cuda_runtime.h>
#include <cuda_bf16.h>
#include <stdint.h>
#include <math.h>

#define TSTEPS 512
#define TOTAL  (TSTEPS * 64 * 1024)      // 33554432 floats per output copy
#define NBLK2  64                        // phase-2 persistent CTAs
#define PLANE_X 33554432u                // 32768*1024 halves per X plane

// ---------------- static device scratch (no allocation) ----------------
__device__ __align__(16) float          g_P[TOTAL];                 // X@Wx+b (fp32)
__device__ __align__(16) __nv_bfloat16  g_Xb[2u * PLANE_X];         // [plane][row 32768][k 1024]
__device__ __align__(16) __nv_bfloat16  g_Wxb[2u * 1024 * 1024];    // [plane][n][k] = Wx[k][n]
__device__ __align__(16) __nv_bfloat16  g_Whb[2u * 1024 * 1024];    // [plane][n][k] = Wh[k][n]
__device__ __align__(16) __nv_bfloat16  g_Sb[2][2 * 65536];         // ping-pong [plane][64 r][1024 k]
__device__ unsigned g_cnt = 0, g_phase = 0;

#define SWZ(o) ((o) ^ (((o) >> 3) & 0x70))

// ---------------- helpers ----------------
__device__ __forceinline__ uint32_t smem_u32(const void* p) {
    uint32_t a;
    asm("{ .reg .u64 t; cvta.to.shared.u64 t, %1; cvt.u32.u64 %0, t; }" : "=r"(a) : "l"(p));
    return a;
}
__device__ __forceinline__ void ldsm4(uint32_t* r, uint32_t addr) {
    asm volatile("ldmatrix.sync.aligned.m8n8.x4.shared.b16 {%0,%1,%2,%3}, [%4];"
                 : "=r"(r[0]), "=r"(r[1]), "=r"(r[2]), "=r"(r[3]) : "r"(addr));
}
__device__ __forceinline__ void mma_bf16(float* c, const uint32_t* a, const uint32_t* b) {
    asm volatile(
        "mma.sync.aligned.m16n8k16.row.col.f32.bf16.bf16.f32 "
        "{%0,%1,%2,%3}, {%4,%5,%6,%7}, {%8,%9}, {%0,%1,%2,%3};"
        : "+f"(c[0]), "+f"(c[1]), "+f"(c[2]), "+f"(c[3])
        : "r"(a[0]), "r"(a[1]), "r"(a[2]), "r"(a[3]), "r"(b[0]), "r"(b[1]));
}
__device__ __forceinline__ void cp16(uint32_t dst, const void* src) {
    asm volatile("cp.async.cg.shared.global [%0], [%1], 16;" :: "r"(dst), "l"(src) : "memory");
}
__device__ __forceinline__ void cp_commit() { asm volatile("cp.async.commit_group;" ::: "memory"); }
template <int N> __device__ __forceinline__ void cp_wait() {
    asm volatile("cp.async.wait_group %0;" :: "n"(N) : "memory");
}
// tanh(z) = 1 - 2/(exp(2z)+1) via MUFU.EX2 + MUFU.RCP (no libm FMA tail; |err| ~1e-6)
__device__ __forceinline__ float fast_tanh(float z) {
    float e, r;
    asm("ex2.approx.ftz.f32 %0, %1;" : "=f"(e) : "f"(z * 2.8853900817779268f));
    asm("rcp.approx.ftz.f32 %0, %1;" : "=f"(r) : "f"(e + 1.0f));
    return fmaf(-2.0f, r, 1.0f);
}

// ---------------- grid barrier (64 CTAs, monotonic phase; r6-proven) ----------------
__device__ __forceinline__ void grid_bar() {
    __syncthreads();
    if (threadIdx.x == 0) {
        __threadfence();
        unsigned ph = *((volatile unsigned*)&g_phase);
        unsigned old = atomicAdd(&g_cnt, 1u);
        if (old == NBLK2 - 1) {
            g_cnt = 0;
            __threadfence();
            atomicExch(&g_phase, ph + 1u);
        } else {
            while (*((volatile unsigned*)&g_phase) == ph) { }
        }
        __threadfence();
    }
    __syncthreads();
}

// ---------------- conversion kernels ----------------
__global__ void conv_w(const float* __restrict__ W, int which)
{
    __nv_bfloat16* out = which ? g_Whb : g_Wxb;
    __shared__ float sm[64][65];
    const int n0 = blockIdx.x << 6, k0 = blockIdx.y << 6;
    const int tid = threadIdx.x;
#pragma unroll
    for (int it = 0; it < 16; it++) {
        int e = it * 256 + tid;
        int kk = e >> 6, nn = e & 63;
        sm[kk][nn] = W[(size_t)(k0 + kk) * 1024 + n0 + nn];
    }
    __syncthreads();
#pragma unroll
    for (int it = 0; it < 16; it++) {
        int e = it * 256 + tid;
        int nn = e >> 6, kk = e & 63;
        float v = sm[kk][nn];
        __nv_bfloat16 hi = __float2bfloat16(v);
        __nv_bfloat16 lo = __float2bfloat16(v - __bfloat162float(hi));
        size_t o = (size_t)(n0 + nn) * 1024 + k0 + kk;
        out[o]            = hi;
        out[o + 1048576u] = lo;
    }
}

// Each launch converts a CONTIGUOUS half of X: f4 in [base, base + 4194304).
// v in [0, 524288), i stride 524288 -> exact coverage (r12 bug: stride was 1048576).
__global__ void conv_x(const float* __restrict__ X, int base)
{
    int v = blockIdx.x * 256 + threadIdx.x;
#pragma unroll
    for (int i = 0; i < 8; i++) {
        int f4 = base + v + i * 524288;
        const float4 x = ((const float4*)X)[f4];
        size_t e0 = (size_t)f4 << 2;
        float xs[4] = {x.x, x.y, x.z, x.w};
        unsigned short hs[4], ls[4];
#pragma unroll
        for (int q = 0; q < 4; q++) {
            __nv_bfloat16 hv = __float2bfloat16(xs[q]);
            __nv_bfloat16 lv = __float2bfloat16(xs[q] - __bfloat162float(hv));
            hs[q] = __bfloat16_as_ushort(hv); ls[q] = __bfloat16_as_ushort(lv);
        }
        *(ushort4*)(g_Xb + e0)           = make_ushort4(hs[0], hs[1], hs[2], hs[3]);
        *(ushort4*)(g_Xb + e0 + PLANE_X) = make_ushort4(ls[0], ls[1], ls[2], ls[3]);
    }
}

// ---------------- phase 1: P = X@Wx + b (unchanged — 482us, tensor 70%) ----------------
#define P1_SMEM 131072

#define P1_ISSUE(kt) do {                                                              \
    _Pragma("unroll")                                                                  \
    for (int i = 0; i < 8; i++) {                                                      \
        int id = i * 256 + tid;                                                        \
        int ku = id & 7, r = (id >> 3) & 127, p = id >> 10;                            \
        uint32_t off = (uint32_t)((((kt) & 1) << 16) + (p << 14)                       \
                       + SWZ((uint32_t)(r * 128 + ku * 16)));                          \
        cp16(su + off,         g_Xb  + (size_t)p * PLANE_X                             \
             + (size_t)(m0 + r) * 1024 + (kt) * 64 + ku * 8);                          \
        cp16(su + off + 32768, g_Wxb + (size_t)p * 1048576                             \
             + (size_t)(col0 + r) * 1024 + (kt) * 64 + ku * 8);                        \
    }                                                                                  \
    cp_commit();                                                                       \
} while (0)

__global__ void __launch_bounds__(256, 1)
gemm_p1(const float* __restrict__ bias)
{
    extern __shared__ __align__(1024) char dyn[];
    const uint32_t su = smem_u32(dyn);
    const int tid = threadIdx.x, wid = tid >> 5, lane = tid & 31;
    const int col0 = blockIdx.x << 7, m0 = blockIdx.y << 7;

    const int laneR = lane & 7, idq = lane >> 3;
    const int rowA = laneR + ((idq & 1) << 3), k8A = (idq >> 1) << 3;
    const int nB   = laneR + ((idq >> 1) << 3), k8B = (idq & 1) << 3;
    uint32_t swzA[4], swzB[4];
#pragma unroll
    for (int kc = 0; kc < 4; kc++) {
        swzA[kc] = SWZ((uint32_t)(rowA * 128 + (kc * 16 + k8A) * 2));
        swzB[kc] = SWZ((uint32_t)(nB   * 128 + (kc * 16 + k8B) * 2));
    }

    float c[16][4];
#pragma unroll
    for (int q = 0; q < 16; q++)
#pragma unroll
        for (int j = 0; j < 4; j++) c[q][j] = 0.0f;

    P1_ISSUE(0);
    for (int kt = 0; kt < 16; kt++) {
        if (kt < 15) { P1_ISSUE(kt + 1); cp_wait<1>(); } else { cp_wait<0>(); }
        __syncthreads();
        const uint32_t Ab = su + ((kt & 1) << 16) + (wid << 11);
        const uint32_t Bb = su + ((kt & 1) << 16) + 32768;
#pragma unroll
        for (int kc = 0; kc < 4; kc++) {
            uint32_t ah[4], al[4], bb[32];
            ldsm4(ah, Ab + swzA[kc]);
            ldsm4(al, Ab + 16384 + swzA[kc]);
#pragma unroll
            for (int q = 0; q < 8; q++) ldsm4(&bb[q * 4], Bb + q * 2048 + swzB[kc]);
#pragma unroll
            for (int q = 0; q < 8; q++) {
                mma_bf16(c[2 * q],     ah, &bb[q * 4]);
                mma_bf16(c[2 * q + 1], ah, &bb[q * 4 + 2]);
            }
#pragma unroll
            for (int q = 0; q < 8; q++) {
                mma_bf16(c[2 * q],     al, &bb[q * 4]);
                mma_bf16(c[2 * q + 1], al, &bb[q * 4 + 2]);
            }
#pragma unroll
            for (int q = 0; q < 8; q++) ldsm4(&bb[q * 4], Bb + 16384 + q * 2048 + swzB[kc]);
#pragma unroll
            for (int q = 0; q < 8; q++) {
                mma_bf16(c[2 * q],     ah, &bb[q * 4]);
                mma_bf16(c[2 * q + 1], ah, &bb[q * 4 + 2]);
            }
        }
        __syncthreads();
    }

    const int r0 = m0 + (wid << 4) + (lane >> 2);
#pragma unroll
    for (int nb = 0; nb < 16; nb++) {
        int colp = col0 + nb * 8 + ((lane & 3) << 1);
        float2 bb = *(const float2*)&bias[colp];
        *(float2*)&g_P[(size_t)r0 * 1024 + colp]       = make_float2(c[nb][0] + bb.x, c[nb][1] + bb.y);
        *(float2*)&g_P[(size_t)(r0 + 8) * 1024 + colp] = make_float2(c[nb][2] + bb.x, c[nb][3] + bb.y);
    }
}

// ---------------- phase 2: persistent recurrence (6 accum chains + P prefetch) ----------------
// 64 CTAs x 128 thr (4 warps, 16 rows each; all 16 cols per warp). CTA owns 16 columns.
// smem: A ring 4 x 32K @0 | Wh 64K @131072 | stg @196608 | red @200960 | pP @202240
#define P2_SMEM 206464

#define P2_ISSUE(ss) do {                                                              \
    _Pragma("unroll")                                                                  \
    for (int i = 0; i < 16; i++) {                                                     \
        int id = i * 128 + tid;                                                        \
        int ku = id & 15, r = (id >> 4) & 63, p = id >> 10;                            \
        uint32_t off = (uint32_t)((((ss) & 3) << 15)                                   \
                       + (((p * 4 + (r >> 4)) * 2 + (ku >> 3)) << 11)                  \
                       + SWZ((uint32_t)((r & 15) * 128 + (ku & 7) * 16)));             \
        cp16(su + off, Sb + (size_t)p * 65536 + (size_t)r * 1024 + (ss) * 128 + ku * 8); \
    }                                                                                  \
    cp_commit();                                                                       \
} while (0)

__global__ void __launch_bounds__(128, 1)
rnn_p2(const float* __restrict__ state0, float* __restrict__ out)
{
    extern __shared__ __align__(1024) char dyn[];
    const uint32_t su = smem_u32(dyn);
    const int tid = threadIdx.x, wid = tid >> 5, lane = tid & 31;
    const int n0 = blockIdx.x << 4;

    const int laneR = lane & 7, idq = lane >> 3;
    const int rowA = laneR + ((idq & 1) << 3), k8A = (idq >> 1) << 3;
    const int nB   = laneR + ((idq >> 1) << 3), k8B = (idq & 1) << 3;
    uint32_t swzA[4], swzB[4];
#pragma unroll
    for (int kc = 0; kc < 4; kc++) {
        swzA[kc] = SWZ((uint32_t)(rowA * 128 + (kc * 16 + k8A) * 2));
        swzB[kc] = SWZ((uint32_t)(nB   * 128 + (kc * 16 + k8B) * 2));
    }

    // resident Wh slice @131072: [2p][16 s64][16 n][128B] swizzled (64 KB)
#pragma unroll 4
    for (int i = 0; i < 32; i++) {
        int id = i * 128 + tid;
        int ku = id & 127, n = (id >> 7) & 15, p = id >> 11;
        uint4 v = *(const uint4*)(g_Whb + (size_t)p * 1048576 + (size_t)(n0 + n) * 1024 + ku * 8);
        uint32_t off = 131072u + (uint32_t)(((p * 16 + (ku >> 3)) << 11)
                       + SWZ((uint32_t)(n * 128 + (ku & 7) * 16)));
        *(uint4*)(dyn + off) = v;
    }
    // init ping state from state0
    {
        int id = blockIdx.x * 128 + tid;
#pragma unroll
        for (int i = 0; i < 2; i++) {
            int f4 = id + i * 8192;                // 16384 float4
            float4 x = ((const float4*)state0)[f4];
            size_t e0 = (size_t)f4 << 2;
            float xs[4] = {x.x, x.y, x.z, x.w};
            unsigned short hs[4], ls[4];
#pragma unroll
            for (int q = 0; q < 4; q++) {
                __nv_bfloat16 hv = __float2bfloat16(xs[q]);
                __nv_bfloat16 lv = __float2bfloat16(xs[q] - __bfloat162float(hv));
                hs[q] = __bfloat16_as_ushort(hv); ls[q] = __bfloat16_as_ushort(lv);
            }
            *(ushort4*)(&g_Sb[0][e0])         = make_ushort4(hs[0], hs[1], hs[2], hs[3]);
            *(ushort4*)(&g_Sb[0][e0 + 65536]) = make_ushort4(ls[0], ls[1], ls[2], ls[3]);
        }
    }
    __threadfence();
    grid_bar();

    float* stg  = (float*)(dyn + 196608);          // [64][17]
    float* psum = (float*)(dyn + 200960);          // [8][16]
    float* psq  = (float*)(dyn + 201472);          // [8][16]
    float* cmu  = (float*)(dyn + 201984);          // [16]
    float* cinv = (float*)(dyn + 202048);          // [16]
    float* pP   = (float*)(dyn + 202240);          // [64][16]
    const int j = tid & 15, hg = tid >> 4;

    for (int t = 0; t < TSTEPS; t++) {
        const __nv_bfloat16* Sb = g_Sb[t & 1];

        // P[t] prefetch — own group, committed FIRST (retires with slab 0's wait)
        {
            const float* Pt = g_P + (size_t)t * 65536 + n0;
            cp16(su + 202240 + tid * 16,        Pt + (size_t)(tid >> 2) * 1024 + ((tid & 3) << 2));
            cp16(su + 202240 + 2048 + tid * 16, Pt + (size_t)((tid >> 2) + 32) * 1024 + ((tid & 3) << 2));
            cp_commit();
        }
        P2_ISSUE(0); P2_ISSUE(1); P2_ISSUE(2);

        // 6 independent accumulator chains: term x column-half
        float a0[4] = {0, 0, 0, 0}, a1[4] = {0, 0, 0, 0}, a2[4] = {0, 0, 0, 0};
        float b0[4] = {0, 0, 0, 0}, b1[4] = {0, 0, 0, 0}, b2[4] = {0, 0, 0, 0};
        for (int s = 0; s < 8; s++) {
            if (s <= 5) cp_wait<2>(); else if (s == 6) cp_wait<1>(); else cp_wait<0>();
            __syncthreads();
            if (s < 5) P2_ISSUE(s + 3);            // overwrites stage (s-1)&3 — dead post-sync
#pragma unroll
            for (int kc = 0; kc < 8; kc++) {
                uint32_t ah[4], al[4], bh[4], bl[4];
                uint32_t Ab = su + ((s & 3) << 15) + (wid << 12) + ((kc >> 2) << 11);
                uint32_t Bb = su + 131072 + ((s * 2 + (kc >> 2)) << 11);
                ldsm4(ah, Ab + swzA[kc & 3]);
                ldsm4(al, Ab + 16384 + swzA[kc & 3]);
                ldsm4(bh, Bb + swzB[kc & 3]);
                ldsm4(bl, Bb + 32768 + swzB[kc & 3]);
                mma_bf16(a0, ah, bh); mma_bf16(b0, ah, bh + 2);
                mma_bf16(a1, al, bh); mma_bf16(b1, al, bh + 2);
                mma_bf16(a2, ah, bl); mma_bf16(b2, ah, bl + 2);
            }
            __syncthreads();
        }

        // ---- epilogue: stage C (= sum of 3 chains), +P, tanh, per-column BN ----
        {
            int rr = (wid << 4) + (lane >> 2);
            int cc = (lane & 3) << 1;
            stg[rr * 17 + cc]           = a0[0] + a1[0] + a2[0];
            stg[rr * 17 + cc + 1]       = a0[1] + a1[1] + a2[1];
            stg[(rr + 8) * 17 + cc]     = a0[2] + a1[2] + a2[2];
            stg[(rr + 8) * 17 + cc + 1] = a0[3] + a1[3] + a2[3];
            stg[rr * 17 + 8 + cc]           = b0[0] + b1[0] + b2[0];
            stg[rr * 17 + 8 + cc + 1]       = b0[1] + b1[1] + b2[1];
            stg[(rr + 8) * 17 + 8 + cc]     = b0[2] + b1[2] + b2[2];
            stg[(rr + 8) * 17 + 8 + cc + 1] = b0[3] + b1[3] + b2[3];
        }
        __syncthreads();

        float hv[8], ps = 0.0f, pq = 0.0f;
#pragma unroll
        for (int i = 0; i < 8; i++) {
            int r = hg * 8 + i;
            float z = stg[r * 17 + j] + pP[r * 16 + j];
            float h = fast_tanh(z);
            hv[i] = h; ps += h; pq += h * h;
        }
        psum[hg * 16 + j] = ps;
        psq[hg * 16 + j]  = pq;
        __syncthreads();
        if (tid < 16) {
            float s = 0.0f, q = 0.0f;
#pragma unroll
            for (int g2 = 0; g2 < 8; g2++) { s += psum[g2 * 16 + tid]; q += psq[g2 * 16 + tid]; }
            float mu  = s * (1.0f / 64.0f);
            float var = q * (1.0f / 64.0f) - mu * mu;
            cmu[tid]  = mu;
            cinv[tid] = rsqrtf(var + 1e-5f);
        }
        __syncthreads();
        {
            float mu = cmu[j], inv = cinv[j];
            __nv_bfloat16* Sn = g_Sb[(t + 1) & 1];
#pragma unroll
            for (int i = 0; i < 8; i++) {
                int r = hg * 8 + i;
                float sv = (hv[i] - mu) * inv;
                size_t o = ((size_t)t * 64 + r) * 1024 + n0 + j;
                out[o]                 = sv;
                out[o + (size_t)TOTAL] = sv;
                __nv_bfloat16 hb = __float2bfloat16(sv);
                __nv_bfloat16 lb = __float2bfloat16(sv - __bfloat162float(hb));
                Sn[(size_t)r * 1024 + n0 + j]         = hb;
                Sn[65536 + (size_t)r * 1024 + n0 + j] = lb;
            }
        }
        __threadfence();
        grid_bar();
    }
}

// ---------------------------------------------------------------------------
extern "C" void kernel_launch(void* const* d_in, const int* in_sizes, int n_in,
                              void* d_out, int out_size)
{
    const float* X    = (const float*)d_in[0];   // [512,64,1024]
    const float* S0   = (const float*)d_in[1];   // [1,64,1024]
    const float* Wx   = (const float*)d_in[2];   // [1024,1024]
    const float* Wh   = (const float*)d_in[3];   // [1024,1024]
    const float* bias = (const float*)d_in[4];   // [1024]
    float* out = (float*)d_out;

    cudaFuncSetAttribute(gemm_p1, cudaFuncAttributeMaxDynamicSharedMemorySize, P1_SMEM);
    cudaFuncSetAttribute(rnn_p2,  cudaFuncAttributeMaxDynamicSharedMemorySize, P2_SMEM);

    conv_w<<<dim3(16, 16), 256>>>(Wx, 0);
    conv_w<<<dim3(16, 16), 256>>>(Wh, 1);
    conv_x<<<2048, 256>>>(X, 0);
    conv_x<<<2048, 256>>>(X, 4194304);
    gemm_p1<<<dim3(8, 256), 256, P1_SMEM>>>(bias);
    rnn_p2<<<NBLK2, 128, P2_SMEM>>>(S0, out);
}